// round 10
// baseline (speedup 1.0000x reference)
#include <cuda_runtime.h>
#include <cuda_bf16.h>
#include <math.h>

#define HIDDEN 64
#define BATCH  16
#define TSTEPS 16
#define NNPOS  4096
#define TILE_P 256
#define NTHREADS 512

typedef unsigned int u32;

// ---- smem layout (bytes) ----
#define A_STRIDE 144            // 64 bf16 = 128B padded to 144 (conflict-free LDSM)
#define B_STRIDE 400            // 192 bf16 = 384B padded to 400
#define APLANE   (258 * A_STRIDE)          // 37152
#define BPLANE   (128 * B_STRIDE)          // 51200
#define OFF_A    0                          // 2 planes: hi, lo
#define OFF_B    (2 * APLANE)               // 74304; 2 planes
#define OFF_X    (OFF_B + 2 * BPLANE)       // 176704; 258 floats
#define OFF_WX   (OFF_X + 258 * 4)          // 177736; 128*3 floats
#define OFF_BIAS (OFF_WX + 128 * 3 * 4)     // 179272; 128 floats
#define SMEM_BYTES (OFF_BIAS + 512)         // 179784

// ---- persistent scratch ----
// weight image: [hs][plane][n][192] bf16, n-row: gate=(n>>3)&3, chl=(n>>5)*8+(n&7)
__device__ __align__(16) __nv_bfloat16 g_wimg[2 * 2 * 128 * 192];
__device__ __align__(16) __nv_bfloat16 g_hp[2][2][(size_t)BATCH * NNPOS * HIDDEN]; // [buf][plane][(b*NN+p)*64+ch]
__device__ __align__(16) float         g_c[(size_t)BATCH * NNPOS * HIDDEN];

__device__ __forceinline__ float sigm(float v)  { return 1.f / (1.f + __expf(-v)); }
__device__ __forceinline__ float tanhq(float v) { return 1.f - 2.f / (__expf(2.f * v) + 1.f); }

__device__ __forceinline__ u32 smem_u32(const void* p) {
    u32 a; asm("{ .reg .u64 t; cvta.to.shared.u64 t, %1; cvt.u32.u64 %0, t; }" : "=r"(a) : "l"(p));
    return a;
}

__device__ __forceinline__ void mma16816(float* c, const u32* a, const u32* bf) {
    asm volatile(
        "mma.sync.aligned.m16n8k16.row.col.f32.bf16.bf16.f32 "
        "{%0,%1,%2,%3},{%4,%5,%6,%7},{%8,%9},{%0,%1,%2,%3};"
        : "+f"(c[0]), "+f"(c[1]), "+f"(c[2]), "+f"(c[3])
        : "r"(a[0]), "r"(a[1]), "r"(a[2]), "r"(a[3]), "r"(bf[0]), "r"(bf[1]));
}

__device__ __forceinline__ void ldsm4(u32& r0, u32& r1, u32& r2, u32& r3, u32 addr) {
    asm volatile("ldmatrix.sync.aligned.m8n8.x4.shared.b16 {%0,%1,%2,%3}, [%4];"
        : "=r"(r0), "=r"(r1), "=r"(r2), "=r"(r3) : "r"(addr));
}

// ---- setup: weight image ----
__global__ void repack_img(const float* __restrict__ conv_w) {
    int idx = blockIdx.x * blockDim.x + threadIdx.x;
    if (idx >= 2 * 128 * 192) return;
    int hs  = idx / 24576;
    int rem = idx % 24576;
    int n = rem / 192, k = rem % 192;
    int gate = (n >> 3) & 3;
    int chl  = (n >> 5) * 8 + (n & 7);
    int oc = gate * 64 + hs * 32 + chl;
    int kh = k / 64, ic = k % 64;
    float w = conv_w[((oc * 65 + (ic + 1)) * 3 + kh) * 3 + 1];
    __nv_bfloat16 whi = __float2bfloat16(w);
    __nv_bfloat16 wlo = __float2bfloat16(w - __bfloat162float(whi));
    g_wimg[((size_t)(hs * 2 + 0) * 128 + n) * 192 + k] = whi;
    g_wimg[((size_t)(hs * 2 + 1) * 128 + n) * 192 + k] = wlo;
}

__global__ void zero_state() {
    size_t i = (size_t)blockIdx.x * blockDim.x + threadIdx.x;
    size_t stride = (size_t)gridDim.x * blockDim.x;
    const size_t nc = (size_t)BATCH * NNPOS * HIDDEN;
    for (size_t j = i; j < nc; j += stride) g_c[j] = 0.f;
    u32* h0 = (u32*)&g_hp[0][0][0];            // both planes of buf0 contiguous
    for (size_t j = i; j < nc; j += stride) h0[j] = 0u;
}

// ---- one timestep: 512 threads, 16 warps, warp tile 64x32, LDSM + fused 3-stream ----
__global__ void __launch_bounds__(NTHREADS, 1)
lstm_step(const float* __restrict__ x, const float* __restrict__ conv_w,
          const float* __restrict__ conv_b, int t) {
    extern __shared__ unsigned char sm[];
    const int tid = threadIdx.x, wid = tid >> 5, lane = tid & 31;
    const int g = lane >> 2, tq = lane & 3;
    const int p0 = blockIdx.x * TILE_P;
    const int hs = blockIdx.y;
    const int b  = blockIdx.z;
    const int rd = t & 1, wr = rd ^ 1;

    // ---- stage B: 2 planes x 128 rows x 24 uint4 ----
    {
        const uint4* src = (const uint4*)(g_wimg + (size_t)hs * 2 * 128 * 192);
        #pragma unroll
        for (int m = tid; m < 2 * 128 * 24; m += NTHREADS) {
            int pl = m / 3072, r = (m % 3072) / 24, c = m % 24;
            *(uint4*)(sm + OFF_B + pl * BPLANE + r * B_STRIDE + c * 16) = src[m];
        }
    }
    // ---- stage A (h rows p0-1..p0+256): 2 planes x 258 rows x 8 uint4 ----
    {
        const uint4 z4 = make_uint4(0, 0, 0, 0);
        #pragma unroll
        for (int m = tid; m < 2 * 258 * 8; m += NTHREADS) {
            int pl = m / 2064, r = (m % 2064) / 8, c = m % 8;
            int pos = p0 - 1 + r;
            uint4 v = z4;
            if (pos >= 0 && pos < NNPOS)
                v = ((const uint4*)&g_hp[rd][pl][((size_t)b * NNPOS + pos) * 64])[c];
            *(uint4*)(sm + OFF_A + pl * APLANE + r * A_STRIDE + c * 16) = v;
        }
    }
    // ---- stage x, wx, bias ----
    if (tid < 258) {
        int pos = p0 - 1 + tid;
        ((float*)(sm + OFF_X))[tid] =
            (pos >= 0 && pos < NNPOS) ? x[((size_t)b * TSTEPS + t) * NNPOS + pos] : 0.f;
    }
    if (tid >= 384 && tid < 512) {
        int n = tid - 384;
        int gate = (n >> 3) & 3;
        int chl  = (n >> 5) * 8 + (n & 7);
        int oc = gate * 64 + hs * 32 + chl;
        ((float*)(sm + OFF_BIAS))[n] = conv_b[oc];
        #pragma unroll
        for (int kh = 0; kh < 3; kh++)
            ((float*)(sm + OFF_WX))[n * 3 + kh] = conv_w[((oc * 65 + 0) * 3 + kh) * 3 + 1];
    }
    __syncthreads();

    // ---- mainloop: 16 warps, warp tile 64x32; LDSM frags, fused hi*hi+lo*hi+hi*lo ----
    const int wm = wid >> 2, wn = wid & 3;
    float C[4][4][4];
    #pragma unroll
    for (int mt = 0; mt < 4; mt++)
        #pragma unroll
        for (int nt = 0; nt < 4; nt++)
            #pragma unroll
            for (int r = 0; r < 4; r++) C[mt][nt][r] = 0.f;

    const u32 sbase = smem_u32(sm);
    const int lrow = lane & 15, lcol = (lane >> 4) * 16;
    // per-lane LDSM base addresses
    const u32 a_base = sbase + OFF_A + (u32)((wm * 64 + lrow) * A_STRIDE + lcol);
    const u32 b_base = sbase + OFF_B + (u32)((wn * 32 + lrow) * B_STRIDE + lcol);

    #pragma unroll
    for (int kh = 0; kh < 3; kh++) {
        #pragma unroll
        for (int kk = 0; kk < 4; kk++) {
            const u32 koff = (u32)(kh * 128 + kk * 32);
            // B fragments: 2 ldsm4 per plane (each covers 2 nt)
            u32 bh[4][2], bl[4][2];
            #pragma unroll
            for (int pr = 0; pr < 2; pr++) {
                u32 ba = b_base + (u32)(pr * 16 * B_STRIDE) + koff;
                ldsm4(bh[2 * pr][0], bh[2 * pr + 1][0], bh[2 * pr][1], bh[2 * pr + 1][1], ba);
                ldsm4(bl[2 * pr][0], bl[2 * pr + 1][0], bl[2 * pr][1], bl[2 * pr + 1][1], ba + BPLANE);
            }
            #pragma unroll
            for (int mt = 0; mt < 4; mt++) {
                u32 aa = a_base + (u32)((mt * 16 + kh) * A_STRIDE) + (u32)(kk * 32);
                u32 ah[4], al[4];
                ldsm4(ah[0], ah[1], ah[2], ah[3], aa);
                ldsm4(al[0], al[1], al[2], al[3], aa + APLANE);
                #pragma unroll
                for (int nt = 0; nt < 4; nt++) {
                    mma16816(C[mt][nt], ah, bh[nt]);   // hi*hi
                    mma16816(C[mt][nt], al, bh[nt]);   // lo*hi
                    mma16816(C[mt][nt], ah, bl[nt]);   // hi*lo
                }
            }
        }
    }

    // ---- epilogue: nt == gate (n = wn*32 + gate*8 + 2tq + lsb) ----
    const float* xs  = (const float*)(sm + OFF_X);
    const float* wxs = (const float*)(sm + OFF_WX);
    const float* bss = (const float*)(sm + OFF_BIAS);

    #pragma unroll
    for (int mt = 0; mt < 4; mt++) {
        #pragma unroll
        for (int rh = 0; rh < 2; rh++) {
            const int prow = wm * 64 + mt * 16 + g + rh * 8;
            const int pos  = p0 + prow;
            const float xm1 = xs[prow], x0 = xs[prow + 1], xp1 = xs[prow + 2];
            const int chl = wn * 8 + 2 * tq;
            const size_t base = ((size_t)b * NNPOS + pos) * 64 + hs * 32 + chl;
            float2 cold = *(const float2*)(g_c + base);
            float cc[2], hh[2];
            #pragma unroll
            for (int lsb = 0; lsb < 2; lsb++) {
                const int nb = wn * 32 + 2 * tq + lsb;
                float vi = C[mt][0][rh * 2 + lsb] + bss[nb]      + wxs[nb * 3]        * xm1 + wxs[nb * 3 + 1]        * x0 + wxs[nb * 3 + 2]        * xp1;
                float vf = C[mt][1][rh * 2 + lsb] + bss[nb + 8]  + wxs[(nb + 8) * 3]  * xm1 + wxs[(nb + 8) * 3 + 1]  * x0 + wxs[(nb + 8) * 3 + 2]  * xp1;
                float vo = C[mt][2][rh * 2 + lsb] + bss[nb + 16] + wxs[(nb + 16) * 3] * xm1 + wxs[(nb + 16) * 3 + 1] * x0 + wxs[(nb + 16) * 3 + 2] * xp1;
                float vg = C[mt][3][rh * 2 + lsb] + bss[nb + 24] + wxs[(nb + 24) * 3] * xm1 + wxs[(nb + 24) * 3 + 1] * x0 + wxs[(nb + 24) * 3 + 2] * xp1;
                float co = lsb ? cold.y : cold.x;
                float c2 = sigm(vf) * co + sigm(vi) * tanhq(vg);
                cc[lsb] = c2;
                hh[lsb] = sigm(vo) * tanhq(c2);
            }
            *(float2*)(g_c + base) = make_float2(cc[0], cc[1]);
            __nv_bfloat162 vhi, vlo;
            vhi.x = __float2bfloat16(hh[0]);
            vhi.y = __float2bfloat16(hh[1]);
            vlo.x = __float2bfloat16(hh[0] - __bfloat162float(vhi.x));
            vlo.y = __float2bfloat16(hh[1] - __bfloat162float(vhi.y));
            *(__nv_bfloat162*)&g_hp[wr][0][base] = vhi;
            *(__nv_bfloat162*)&g_hp[wr][1][base] = vlo;
        }
    }
}

// ---- final 1x1 conv + broadcast over TS (final h in buf 0) ----
__global__ void __launch_bounds__(256)
fc_kernel(const float* __restrict__ fc_w, const float* __restrict__ fc_b,
          float* __restrict__ out) {
    __shared__ float w_s[HIDDEN];
    int tid = threadIdx.x;
    if (tid < HIDDEN) w_s[tid] = fc_w[tid];
    __syncthreads();

    int b = blockIdx.y;
    int n = blockIdx.x * 256 + tid;
    const __nv_bfloat16* hhi = &g_hp[0][0][((size_t)b * NNPOS + n) * 64];
    const __nv_bfloat16* hlo = &g_hp[0][1][((size_t)b * NNPOS + n) * 64];
    float acc = fc_b[0];
    #pragma unroll
    for (int ch = 0; ch < HIDDEN; ch++)
        acc += (__bfloat162float(hhi[ch]) + __bfloat162float(hlo[ch])) * w_s[ch];

    #pragma unroll
    for (int t = 0; t < TSTEPS; t++)
        out[((size_t)b * TSTEPS + t) * NNPOS + n] = acc;
}

extern "C" void kernel_launch(void* const* d_in, const int* in_sizes, int n_in,
                              void* d_out, int out_size) {
    const float* x      = (const float*)d_in[0];  // [16,16,4096,1]
    const float* conv_w = (const float*)d_in[1];  // [256,65,3,3]
    const float* conv_b = (const float*)d_in[2];  // [256]
    const float* fc_w   = (const float*)d_in[3];  // [1,64,1,1]
    const float* fc_b   = (const float*)d_in[4];  // [1]
    float* out = (float*)d_out;                   // [16,16,4096,1]

    cudaFuncSetAttribute(lstm_step, cudaFuncAttributeMaxDynamicSharedMemorySize, SMEM_BYTES);

    repack_img<<<(2 * 128 * 192 + 255) / 256, 256>>>(conv_w);
    zero_state<<<1024, 256>>>();

    for (int t = 0; t < TSTEPS; t++)
        lstm_step<<<dim3(NNPOS / TILE_P, 2, BATCH), NTHREADS, SMEM_BYTES>>>(x, conv_w, conv_b, t);

    fc_kernel<<<dim3(NNPOS / 256, BATCH), 256>>>(fc_w, fc_b, out);
}

// round 11
// speedup vs baseline: 1.0806x; 1.0806x over previous
#include <cuda_runtime.h>
#include <cuda_bf16.h>
#include <math.h>

#define HIDDEN 64
#define BATCH  16
#define TSTEPS 16
#define NNPOS  4096
#define TILE_P 256
#define NTHREADS 512

typedef unsigned int u32;

// ---- smem layout (bytes) ----
#define A_STRIDE 144            // 64 bf16 = 128B padded to 144 (conflict-free frags)
#define B_STRIDE 400            // 192 bf16 = 384B padded to 400
#define APLANE   (258 * A_STRIDE)          // 37152
#define BPLANE   (128 * B_STRIDE)          // 51200
#define OFF_A    0                          // 2 planes: hi, lo
#define OFF_B    (2 * APLANE)               // 74304; 2 planes
#define OFF_X    (OFF_B + 2 * BPLANE)       // 176704; 258 floats
#define OFF_WX   (OFF_X + 258 * 4)          // 177736; 128*3 floats
#define OFF_BIAS (OFF_WX + 128 * 3 * 4)     // 179272; 128 floats
#define SMEM_BYTES (OFF_BIAS + 512)         // 179784

// ---- persistent scratch ----
// weight image: [hs][plane][n][192] bf16, n-row: gate=(n>>3)&3, chl=(n>>5)*8+(n&7)
__device__ __align__(16) __nv_bfloat16 g_wimg[2 * 2 * 128 * 192];
__device__ __align__(16) __nv_bfloat16 g_hp[2][2][(size_t)BATCH * NNPOS * HIDDEN]; // [buf][plane][(b*NN+p)*64+ch]
__device__ __align__(16) float         g_c[(size_t)BATCH * NNPOS * HIDDEN];

__device__ __forceinline__ float sigm(float v)  { return 1.f / (1.f + __expf(-v)); }
__device__ __forceinline__ float tanhq(float v) { return 1.f - 2.f / (__expf(2.f * v) + 1.f); }

__device__ __forceinline__ void mma16816(float* c, const u32* a, const u32* bf) {
    asm volatile(
        "mma.sync.aligned.m16n8k16.row.col.f32.bf16.bf16.f32 "
        "{%0,%1,%2,%3},{%4,%5,%6,%7},{%8,%9},{%0,%1,%2,%3};"
        : "+f"(c[0]), "+f"(c[1]), "+f"(c[2]), "+f"(c[3])
        : "r"(a[0]), "r"(a[1]), "r"(a[2]), "r"(a[3]), "r"(bf[0]), "r"(bf[1]));
}

// ---- setup: weight image ----
__global__ void repack_img(const float* __restrict__ conv_w) {
    int idx = blockIdx.x * blockDim.x + threadIdx.x;
    if (idx >= 2 * 128 * 192) return;
    int hs  = idx / 24576;
    int rem = idx % 24576;
    int n = rem / 192, k = rem % 192;
    int gate = (n >> 3) & 3;
    int chl  = (n >> 5) * 8 + (n & 7);
    int oc = gate * 64 + hs * 32 + chl;
    int kh = k / 64, ic = k % 64;
    float w = conv_w[((oc * 65 + (ic + 1)) * 3 + kh) * 3 + 1];
    __nv_bfloat16 whi = __float2bfloat16(w);
    __nv_bfloat16 wlo = __float2bfloat16(w - __bfloat162float(whi));
    g_wimg[((size_t)(hs * 2 + 0) * 128 + n) * 192 + k] = whi;
    g_wimg[((size_t)(hs * 2 + 1) * 128 + n) * 192 + k] = wlo;
}

__global__ void zero_state() {
    size_t i = (size_t)blockIdx.x * blockDim.x + threadIdx.x;
    size_t stride = (size_t)gridDim.x * blockDim.x;
    const size_t nc = (size_t)BATCH * NNPOS * HIDDEN;
    for (size_t j = i; j < nc; j += stride) g_c[j] = 0.f;
    u32* h0 = (u32*)&g_hp[0][0][0];            // both planes of buf0 contiguous
    for (size_t j = i; j < nc; j += stride) h0[j] = 0u;
}

// ---- one timestep: 512 threads, 16 warps, warp tile 64x32, de-serialized 3-stream ----
__global__ void __launch_bounds__(NTHREADS, 1)
lstm_step(const float* __restrict__ x, const float* __restrict__ conv_w,
          const float* __restrict__ conv_b, int t) {
    extern __shared__ unsigned char sm[];
    const int tid = threadIdx.x, wid = tid >> 5, lane = tid & 31;
    const int g = lane >> 2, tq = lane & 3;
    const int p0 = blockIdx.x * TILE_P;
    const int hs = blockIdx.y;
    const int b  = blockIdx.z;
    const int rd = t & 1, wr = rd ^ 1;

    // ---- stage B: 2 planes x 128 rows x 24 uint4 ----
    {
        const uint4* src = (const uint4*)(g_wimg + (size_t)hs * 2 * 128 * 192);
        #pragma unroll
        for (int m = tid; m < 2 * 128 * 24; m += NTHREADS) {
            int pl = m / 3072, r = (m % 3072) / 24, c = m % 24;
            *(uint4*)(sm + OFF_B + pl * BPLANE + r * B_STRIDE + c * 16) = src[m];
        }
    }
    // ---- stage A (h rows p0-1..p0+256): 2 planes x 258 rows x 8 uint4 ----
    {
        const uint4 z4 = make_uint4(0, 0, 0, 0);
        #pragma unroll
        for (int m = tid; m < 2 * 258 * 8; m += NTHREADS) {
            int pl = m / 2064, r = (m % 2064) / 8, c = m % 8;
            int pos = p0 - 1 + r;
            uint4 v = z4;
            if (pos >= 0 && pos < NNPOS)
                v = ((const uint4*)&g_hp[rd][pl][((size_t)b * NNPOS + pos) * 64])[c];
            *(uint4*)(sm + OFF_A + pl * APLANE + r * A_STRIDE + c * 16) = v;
        }
    }
    // ---- stage x, wx, bias ----
    if (tid < 258) {
        int pos = p0 - 1 + tid;
        ((float*)(sm + OFF_X))[tid] =
            (pos >= 0 && pos < NNPOS) ? x[((size_t)b * TSTEPS + t) * NNPOS + pos] : 0.f;
    }
    if (tid >= 384 && tid < 512) {
        int n = tid - 384;
        int gate = (n >> 3) & 3;
        int chl  = (n >> 5) * 8 + (n & 7);
        int oc = gate * 64 + hs * 32 + chl;
        ((float*)(sm + OFF_BIAS))[n] = conv_b[oc];
        #pragma unroll
        for (int kh = 0; kh < 3; kh++)
            ((float*)(sm + OFF_WX))[n * 3 + kh] = conv_w[((oc * 65 + 0) * 3 + kh) * 3 + 1];
    }
    __syncthreads();

    // ---- mainloop: 16 warps, warp tile 64x32; streams issued in nt-sweeps ----
    const int wm = wid >> 2, wn = wid & 3;
    float C[4][4][4];
    #pragma unroll
    for (int mt = 0; mt < 4; mt++)
        #pragma unroll
        for (int nt = 0; nt < 4; nt++)
            #pragma unroll
            for (int r = 0; r < 4; r++) C[mt][nt][r] = 0.f;

    const unsigned char* Arow = sm + OFF_A + (wm * 64 + g) * A_STRIDE + tq * 4;
    const unsigned char* Brow = sm + OFF_B + (wn * 32 + g) * B_STRIDE + tq * 4;

    #pragma unroll 1
    for (int kh = 0; kh < 3; kh++) {
        const unsigned char* Akh = Arow + kh * A_STRIDE;
        const unsigned char* Bkh = Brow + kh * 128;      // k += 64 -> 128 bytes
        #pragma unroll
        for (int kk = 0; kk < 4; kk++) {
            // B fragments for this kk: hi and lo planes (shared by all mt)
            u32 bh[4][2], bl[4][2];
            #pragma unroll
            for (int nt = 0; nt < 4; nt++) {
                const unsigned char* q = Bkh + nt * (8 * B_STRIDE) + kk * 32;
                bh[nt][0] = *(const u32*)q;
                bh[nt][1] = *(const u32*)(q + 16);
                bl[nt][0] = *(const u32*)(q + BPLANE);
                bl[nt][1] = *(const u32*)(q + BPLANE + 16);
            }
            // process mt in pairs; issue 6 nt-sweeps -> same-C reuse distance = 8 HMMAs
            #pragma unroll
            for (int mp = 0; mp < 2; mp++) {
                const int m0 = 2 * mp, m1 = 2 * mp + 1;
                const unsigned char* p0p = Akh + m0 * (16 * A_STRIDE) + kk * 32;
                const unsigned char* p1p = Akh + m1 * (16 * A_STRIDE) + kk * 32;
                u32 ah0[4], al0[4], ah1[4], al1[4];
                ah0[0] = *(const u32*)p0p;
                ah0[1] = *(const u32*)(p0p + 8 * A_STRIDE);
                ah0[2] = *(const u32*)(p0p + 16);
                ah0[3] = *(const u32*)(p0p + 8 * A_STRIDE + 16);
                al0[0] = *(const u32*)(p0p + APLANE);
                al0[1] = *(const u32*)(p0p + APLANE + 8 * A_STRIDE);
                al0[2] = *(const u32*)(p0p + APLANE + 16);
                al0[3] = *(const u32*)(p0p + APLANE + 8 * A_STRIDE + 16);
                ah1[0] = *(const u32*)p1p;
                ah1[1] = *(const u32*)(p1p + 8 * A_STRIDE);
                ah1[2] = *(const u32*)(p1p + 16);
                ah1[3] = *(const u32*)(p1p + 8 * A_STRIDE + 16);
                al1[0] = *(const u32*)(p1p + APLANE);
                al1[1] = *(const u32*)(p1p + APLANE + 8 * A_STRIDE);
                al1[2] = *(const u32*)(p1p + APLANE + 16);
                al1[3] = *(const u32*)(p1p + APLANE + 8 * A_STRIDE + 16);

                #pragma unroll
                for (int nt = 0; nt < 4; nt++) mma16816(C[m0][nt], ah0, bh[nt]); // hi*hi mt0
                #pragma unroll
                for (int nt = 0; nt < 4; nt++) mma16816(C[m1][nt], ah1, bh[nt]); // hi*hi mt1
                #pragma unroll
                for (int nt = 0; nt < 4; nt++) mma16816(C[m0][nt], al0, bh[nt]); // lo*hi mt0
                #pragma unroll
                for (int nt = 0; nt < 4; nt++) mma16816(C[m1][nt], al1, bh[nt]); // lo*hi mt1
                #pragma unroll
                for (int nt = 0; nt < 4; nt++) mma16816(C[m0][nt], ah0, bl[nt]); // hi*lo mt0
                #pragma unroll
                for (int nt = 0; nt < 4; nt++) mma16816(C[m1][nt], ah1, bl[nt]); // hi*lo mt1
            }
        }
    }

    // ---- epilogue: nt == gate (n = wn*32 + gate*8 + 2tq + lsb) ----
    const float* xs  = (const float*)(sm + OFF_X);
    const float* wxs = (const float*)(sm + OFF_WX);
    const float* bss = (const float*)(sm + OFF_BIAS);

    #pragma unroll
    for (int mt = 0; mt < 4; mt++) {
        #pragma unroll
        for (int rh = 0; rh < 2; rh++) {
            const int prow = wm * 64 + mt * 16 + g + rh * 8;
            const int pos  = p0 + prow;
            const float xm1 = xs[prow], x0 = xs[prow + 1], xp1 = xs[prow + 2];
            const int chl = wn * 8 + 2 * tq;
            const size_t base = ((size_t)b * NNPOS + pos) * 64 + hs * 32 + chl;
            float2 cold = *(const float2*)(g_c + base);
            float cc[2], hh[2];
            #pragma unroll
            for (int lsb = 0; lsb < 2; lsb++) {
                const int nb = wn * 32 + 2 * tq + lsb;
                float vi = C[mt][0][rh * 2 + lsb] + bss[nb]      + wxs[nb * 3]        * xm1 + wxs[nb * 3 + 1]        * x0 + wxs[nb * 3 + 2]        * xp1;
                float vf = C[mt][1][rh * 2 + lsb] + bss[nb + 8]  + wxs[(nb + 8) * 3]  * xm1 + wxs[(nb + 8) * 3 + 1]  * x0 + wxs[(nb + 8) * 3 + 2]  * xp1;
                float vo = C[mt][2][rh * 2 + lsb] + bss[nb + 16] + wxs[(nb + 16) * 3] * xm1 + wxs[(nb + 16) * 3 + 1] * x0 + wxs[(nb + 16) * 3 + 2] * xp1;
                float vg = C[mt][3][rh * 2 + lsb] + bss[nb + 24] + wxs[(nb + 24) * 3] * xm1 + wxs[(nb + 24) * 3 + 1] * x0 + wxs[(nb + 24) * 3 + 2] * xp1;
                float co = lsb ? cold.y : cold.x;
                float c2 = sigm(vf) * co + sigm(vi) * tanhq(vg);
                cc[lsb] = c2;
                hh[lsb] = sigm(vo) * tanhq(c2);
            }
            *(float2*)(g_c + base) = make_float2(cc[0], cc[1]);
            __nv_bfloat162 vhi, vlo;
            vhi.x = __float2bfloat16(hh[0]);
            vhi.y = __float2bfloat16(hh[1]);
            vlo.x = __float2bfloat16(hh[0] - __bfloat162float(vhi.x));
            vlo.y = __float2bfloat16(hh[1] - __bfloat162float(vhi.y));
            *(__nv_bfloat162*)&g_hp[wr][0][base] = vhi;
            *(__nv_bfloat162*)&g_hp[wr][1][base] = vlo;
        }
    }
}

// ---- final 1x1 conv + broadcast over TS (final h in buf 0) ----
__global__ void __launch_bounds__(256)
fc_kernel(const float* __restrict__ fc_w, const float* __restrict__ fc_b,
          float* __restrict__ out) {
    __shared__ float w_s[HIDDEN];
    int tid = threadIdx.x;
    if (tid < HIDDEN) w_s[tid] = fc_w[tid];
    __syncthreads();

    int b = blockIdx.y;
    int n = blockIdx.x * 256 + tid;
    const __nv_bfloat16* hhi = &g_hp[0][0][((size_t)b * NNPOS + n) * 64];
    const __nv_bfloat16* hlo = &g_hp[0][1][((size_t)b * NNPOS + n) * 64];
    float acc = fc_b[0];
    #pragma unroll
    for (int ch = 0; ch < HIDDEN; ch++)
        acc += (__bfloat162float(hhi[ch]) + __bfloat162float(hlo[ch])) * w_s[ch];

    #pragma unroll
    for (int t = 0; t < TSTEPS; t++)
        out[((size_t)b * TSTEPS + t) * NNPOS + n] = acc;
}

extern "C" void kernel_launch(void* const* d_in, const int* in_sizes, int n_in,
                              void* d_out, int out_size) {
    const float* x      = (const float*)d_in[0];  // [16,16,4096,1]
    const float* conv_w = (const float*)d_in[1];  // [256,65,3,3]
    const float* conv_b = (const float*)d_in[2];  // [256]
    const float* fc_w   = (const float*)d_in[3];  // [1,64,1,1]
    const float* fc_b   = (const float*)d_in[4];  // [1]
    float* out = (float*)d_out;                   // [16,16,4096,1]

    cudaFuncSetAttribute(lstm_step, cudaFuncAttributeMaxDynamicSharedMemorySize, SMEM_BYTES);

    repack_img<<<(2 * 128 * 192 + 255) / 256, 256>>>(conv_w);
    zero_state<<<1024, 256>>>();

    for (int t = 0; t < TSTEPS; t++)
        lstm_step<<<dim3(NNPOS / TILE_P, 2, BATCH), NTHREADS, SMEM_BYTES>>>(x, conv_w, conv_b, t);

    fc_kernel<<<dim3(NNPOS / 256, BATCH), 256>>>(fc_w, fc_b, out);
}